// round 12
// baseline (speedup 1.0000x reference)
#include <cuda_runtime.h>

#define H 1024
#define S 65536
#define RPB 8                       // rows per block in GEMV (1 row per warp)
#define GEMV_GRID (S / RPB)         // 8192 blocks
#define TAIL_BLOCKS 64

// ---- scratch (device globals; no allocation anywhere) ----
__device__ float g_v[H];                   // v = W^T h
__device__ float g_bm[GEMV_GRID];          // per-block score max
__device__ float g_bs[GEMV_GRID];          // per-block sum of exp(s - m_b)
__device__ float g_pm[TAIL_BLOCKS];        // tail second-level partial max
__device__ float g_ps[TAIL_BLOCKS];        // tail second-level partial sum
__device__ float g_gmax;                   // global max
__device__ float g_inv;                    // 1 / total
__device__ unsigned g_ctr3;                // tail last-block counter
__device__ unsigned g_done;                // (gmax,inv) ready flag

// ---------------------------------------------------------------------------
// K1: v = W^T h. 128 blocks x 256 threads; block b owns columns 8b..8b+7.
// Thread (c = t&7, rg = t>>3): column 8b+c, rows rg+32k, 4 batches of 8
// independent scalar LDGs (MLP=8, tiny reg footprint). SMEM tree over rg.
// b.h is omitted: a constant shift cancels in softmax.
// Block 0 also resets the tail counter/flag for graph replay.
// ---------------------------------------------------------------------------
__global__ __launch_bounds__(256) void k1_prep(const float* __restrict__ hidden,
                                               const float* __restrict__ W) {
    __shared__ float hs[H];
    __shared__ float red[32][9];            // padded
    int t = threadIdx.x;

    if (blockIdx.x == 0 && t == 0) { g_ctr3 = 0; g_done = 0; }

#pragma unroll
    for (int k = 0; k < 4; k++) hs[t + 256 * k] = hidden[t + 256 * k];
    __syncthreads();

    int c  = t & 7;                         // owned column within slab
    int rg = t >> 3;                        // row group 0..31 (rows rg + 32k)
    const float* Wp = W + (size_t)rg * H + blockIdx.x * 8 + c;

    float acc = 0.f;
#pragma unroll
    for (int kb = 0; kb < 32; kb += 8) {
        float w0 = Wp[(size_t)(kb + 0) * 32 * H];
        float w1 = Wp[(size_t)(kb + 1) * 32 * H];
        float w2 = Wp[(size_t)(kb + 2) * 32 * H];
        float w3 = Wp[(size_t)(kb + 3) * 32 * H];
        float w4 = Wp[(size_t)(kb + 4) * 32 * H];
        float w5 = Wp[(size_t)(kb + 5) * 32 * H];
        float w6 = Wp[(size_t)(kb + 6) * 32 * H];
        float w7 = Wp[(size_t)(kb + 7) * 32 * H];
        acc = fmaf(w0, hs[rg + (kb + 0) * 32], acc);
        acc = fmaf(w1, hs[rg + (kb + 1) * 32], acc);
        acc = fmaf(w2, hs[rg + (kb + 2) * 32], acc);
        acc = fmaf(w3, hs[rg + (kb + 3) * 32], acc);
        acc = fmaf(w4, hs[rg + (kb + 4) * 32], acc);
        acc = fmaf(w5, hs[rg + (kb + 5) * 32], acc);
        acc = fmaf(w6, hs[rg + (kb + 6) * 32], acc);
        acc = fmaf(w7, hs[rg + (kb + 7) * 32], acc);
    }
    red[rg][c] = acc;
    __syncthreads();
#pragma unroll
    for (int o = 16; o; o >>= 1) {
        if (rg < o) red[rg][c] += red[rg + o][c];
        __syncthreads();
    }
    if (t < 8) g_v[blockIdx.x * 8 + t] = red[0][t];
}

// ---------------------------------------------------------------------------
// K2: streaming GEMV + partial softmax. (Untouched: measured ~7 TB/s.)
// ---------------------------------------------------------------------------
__global__ __launch_bounds__(256) void k2_gemv(const float* __restrict__ enc,
                                               float* __restrict__ out) {
    __shared__ float4 sv[H / 4];        // 4 KB
    sv[threadIdx.x] = ((const float4*)g_v)[threadIdx.x];
    __syncthreads();

    int warp = threadIdx.x >> 5;
    int lane = threadIdx.x & 31;
    int row  = blockIdx.x * RPB + warp;
    const float4* rp = (const float4*)(enc + (size_t)row * H);

    float4 a[8];
#pragma unroll
    for (int k = 0; k < 8; k++) a[k] = __ldcs(rp + lane + 32 * k);   // MLP=8

    float acc = 0.f;
#pragma unroll
    for (int k = 0; k < 8; k++) {
        float4 vv = sv[lane + 32 * k];
        acc = fmaf(a[k].x, vv.x, acc);
        acc = fmaf(a[k].y, vv.y, acc);
        acc = fmaf(a[k].z, vv.z, acc);
        acc = fmaf(a[k].w, vv.w, acc);
    }
#pragma unroll
    for (int o = 16; o; o >>= 1) acc += __shfl_xor_sync(0xFFFFFFFFu, acc, o);

    __shared__ float ws[RPB];
    if (lane == 0) ws[warp] = acc;
    __syncthreads();

    if (threadIdx.x == 0) {
        float mb = ws[0];
#pragma unroll
        for (int i = 1; i < RPB; i++) mb = fmaxf(mb, ws[i]);
        float sm = 0.f;
#pragma unroll
        for (int i = 0; i < RPB; i++) {
            float e = expf(ws[i] - mb);
            sm += e;
            out[blockIdx.x * RPB + i] = e;
        }
        g_bm[blockIdx.x] = mb;
        g_bs[blockIdx.x] = sm;
    }
}

// ---------------------------------------------------------------------------
// K3 (single tail kernel): two-level softmax finalize + scale.
// 64 blocks x 256 threads (all wave-1 resident -> spin is safe).
//  1) prefetch this thread's output float4 (hides latency behind reduction)
//  2) block reduces its own 128 (m_b, s_b) pairs -> (lm, ls)  [fixed order]
//  3) last-finished block combines the 64 partials with 64 threads ->
//     g_gmax, g_inv; sets g_done
//  4) everyone spins on g_done (set-once -> deterministic), then scales:
//     f = exp(m_b(i) - gmax) * inv, with m_b from this block's own smem.
// ---------------------------------------------------------------------------
__global__ __launch_bounds__(256) void k3_tail(float* __restrict__ out) {
    __shared__ float sm_m[128];
    __shared__ float red[8];
    __shared__ float s_pm[TAIL_BLOCKS], s_ps[TAIL_BLOCKS];
    __shared__ unsigned isLast;
    __shared__ float sgmax, sinv;

    int t = threadIdx.x, b = blockIdx.x;
    int i4 = b * 256 + t;                       // float4 output index

    float4 v = ((const float4*)out)[i4];        // prefetch early

    // ---- level-1: reduce this block's 128 pairs ----
    float m = -3.4e38f, s = 0.f;
    if (t < 128) {
        m = g_bm[b * 128 + t];
        s = g_bs[b * 128 + t];
        sm_m[t] = m;
    }
    float mm = m;
#pragma unroll
    for (int o = 16; o; o >>= 1) mm = fmaxf(mm, __shfl_xor_sync(0xFFFFFFFFu, mm, o));
    if (t < 128 && (t & 31) == 0) red[t >> 5] = mm;
    __syncthreads();
    float lm = fmaxf(fmaxf(red[0], red[1]), fmaxf(red[2], red[3]));

    float e = (t < 128) ? s * expf(m - lm) : 0.f;
#pragma unroll
    for (int o = 16; o; o >>= 1) e += __shfl_xor_sync(0xFFFFFFFFu, e, o);
    if (t < 128 && (t & 31) == 0) red[4 + (t >> 5)] = e;
    __syncthreads();

    if (t == 0) {
        g_pm[b] = lm;
        g_ps[b] = red[4] + red[5] + red[6] + red[7];
        __threadfence();
        unsigned c = atomicAdd(&g_ctr3, 1u);
        isLast = (c == TAIL_BLOCKS - 1) ? 1u : 0u;
    }
    __syncthreads();

    // ---- level-2: last block combines the 64 partials ----
    if (isLast) {
        __threadfence();
        if (t < TAIL_BLOCKS) { s_pm[t] = g_pm[t]; s_ps[t] = g_ps[t]; }
        __syncthreads();
        if (t < 32) {
            float pm = fmaxf(s_pm[t], s_pm[t + 32]);
#pragma unroll
            for (int o = 16; o; o >>= 1) pm = fmaxf(pm, __shfl_xor_sync(0xFFFFFFFFu, pm, o));
            float tot = s_ps[t] * expf(s_pm[t] - pm)
                      + s_ps[t + 32] * expf(s_pm[t + 32] - pm);
#pragma unroll
            for (int o = 16; o; o >>= 1) tot += __shfl_xor_sync(0xFFFFFFFFu, tot, o);
            if (t == 0) {
                g_gmax = pm;
                g_inv  = 1.0f / tot;
                __threadfence();
                atomicExch(&g_done, 1u);
            }
        }
    }

    // ---- wait for (gmax, inv), then scale ----
    if (t == 0) {
        volatile unsigned* d = &g_done;
        while (*d == 0u) { }
        __threadfence();
        sgmax = g_gmax;
        sinv  = g_inv;
    }
    __syncthreads();

    float f = expf(sm_m[t >> 1] - sgmax) * sinv;   // pair (b*128 + t/2) == i4>>1
    v.x *= f; v.y *= f; v.z *= f; v.w *= f;
    ((float4*)out)[i4] = v;
}

extern "C" void kernel_launch(void* const* d_in, const int* in_sizes, int n_in,
                              void* d_out, int out_size) {
    const float* hidden = (const float*)d_in[0];   // [1024]
    const float* enc    = (const float*)d_in[1];   // [65536, 1024]
    const float* W      = (const float*)d_in[2];   // [1024, 1024]
    float* out = (float*)d_out;                    // [65536]

    k1_prep<<<128, 256>>>(hidden, W);
    k2_gemv<<<GEMV_GRID, 256>>>(enc, out);
    k3_tail<<<TAIL_BLOCKS, 256>>>(out);
}